// round 16
// baseline (speedup 1.0000x reference)
#include <cuda_runtime.h>
#include <cuda_fp16.h>
#include <cstdint>
#include <math.h>

#define NN 50000
#define EE 1600000
#define GG 512
#define INF 16
#define HH 128
#define NBLK 49   // ceil(50000/1024)
#define L1PAD 24  // smem halfs per a16 row (bank-conflict-free)
#define L2PAD 136 // smem halfs per h1-agg row

// ---- scratch (static device memory; no allocation anywhere) ----
__device__ float  g_x32[NN * INF];  // dinv-prescaled input features (fp32)
__device__ __half g_half[NN * HH];  // dinv-prescaled h1 (gather source, layer 2)
__device__ __half g_aggh[NN * HH];  // h2 output (pool input)
__device__ __half g_w1h[INF * HH];  // W1 in fp16
__device__ __half g_w2h[HH * HH];   // W2 in fp16
__device__ int    g_degi[NN];       // zeroed at end of every call (and statically)
__device__ int    g_off[NN];
__device__ int    g_csr[EE];        // src ids grouped by dst
__device__ int    g_rank[EE];       // edge rank within its dst bucket
__device__ float  g_dinv[NN];
__device__ int    g_bsum[NBLK];
__device__ int    g_gstart[GG + 1]; // graph segment starts (batch sorted)
__device__ int    g_ctr;            // scan barrier counter (reset by k_poolhead)

// ---------- helpers ----------
__device__ __forceinline__ float4 ldh4(const __half* p) {
    uint2 u = *(const uint2*)p;
    __half2 a, b;
    *(unsigned*)&a = u.x; *(unsigned*)&b = u.y;
    float2 fa = __half22float2(a), fb = __half22float2(b);
    return make_float4(fa.x, fa.y, fb.x, fb.y);
}
__device__ __forceinline__ void ldmx4t(unsigned& r0, unsigned& r1, unsigned& r2,
                                       unsigned& r3, const void* sp) {
    unsigned addr = (unsigned)__cvta_generic_to_shared(sp);
    asm volatile("ldmatrix.sync.aligned.m8n8.x4.trans.shared.b16 {%0,%1,%2,%3}, [%4];"
                 : "=r"(r0), "=r"(r1), "=r"(r2), "=r"(r3) : "r"(addr));
}
__device__ __forceinline__ void mma16816(float* c, unsigned a0, unsigned a1,
                                         unsigned a2, unsigned a3,
                                         unsigned b0, unsigned b1) {
    asm volatile("mma.sync.aligned.m16n8k16.row.col.f32.f16.f16.f32 "
                 "{%0,%1,%2,%3}, {%4,%5,%6,%7}, {%8,%9}, {%0,%1,%2,%3};"
                 : "+f"(c[0]), "+f"(c[1]), "+f"(c[2]), "+f"(c[3])
                 : "r"(a0), "r"(a1), "r"(a2), "r"(a3), "r"(b0), "r"(b1));
}

// histogram of dst; rank = position within dst bucket. 4 edges/thread, int4
// loads. Also detects sorted-batch graph boundaries -> g_gstart.
__global__ void k_deg(const int* __restrict__ ei, const int* __restrict__ batch) {
    int tid = blockIdx.x * blockDim.x + threadIdx.x;
    if (tid < NN) {
        int b1 = batch[tid];
        int b0 = (tid == 0) ? -1 : batch[tid - 1];
        for (int g = b0 + 1; g <= b1; g++) g_gstart[g] = tid;
        if (tid == NN - 1)
            for (int g = b1 + 1; g <= GG; g++) g_gstart[g] = NN;
    }
    int e4 = tid * 4;
    if (e4 >= EE) return;                       // EE % 4 == 0 -> full int4 ok
    int4 d = *(const int4*)&ei[EE + e4];
    int4 r;
    r.x = atomicAdd(&g_degi[d.x], 1);
    r.y = atomicAdd(&g_degi[d.y], 1);
    r.z = atomicAdd(&g_degi[d.z], 1);
    r.w = atomicAdd(&g_degi[d.w], 1);
    *(int4*)&g_rank[e4] = r;
}

// 49 resident blocks: block scan + publish aggregate + W1/W2->fp16 (overlap)
// + spin barrier + global prefix + offsets + dinv + x prescale (fp32).
__global__ void k_scanx(const float* __restrict__ x, const float* __restrict__ W1,
                        const float* __restrict__ W2) {
    __shared__ int spart[256];
    __shared__ int sboff;
    int b = blockIdx.x, t = threadIdx.x;
    int base = b * 1024 + t * 4;
    int d0 = 0, d1 = 0, d2 = 0, d3 = 0;
    if (base + 3 < NN) {
        int4 q = *(const int4*)&g_degi[base];
        d0 = q.x; d1 = q.y; d2 = q.z; d3 = q.w;
    } else {
        if (base + 0 < NN) d0 = g_degi[base + 0];
        if (base + 1 < NN) d1 = g_degi[base + 1];
        if (base + 2 < NN) d2 = g_degi[base + 2];
        if (base + 3 < NN) d3 = g_degi[base + 3];
    }
    int tot = d0 + d1 + d2 + d3;
    spart[t] = tot;
    __syncthreads();
    for (int o = 1; o < 256; o <<= 1) {
        int x2 = (t >= o) ? spart[t - o] : 0;
        __syncthreads();
        spart[t] += x2;
        __syncthreads();
    }
    if (t == 255) g_bsum[b] = spart[255];
    __syncthreads();
    if (t == 0) {
        __threadfence();
        atomicAdd(&g_ctr, 1);
    }

    // overlap work while other blocks publish: W1, W2 -> fp16
    for (int i = b * blockDim.x + t; i < HH * HH; i += NBLK * blockDim.x)
        g_w2h[i] = __float2half_rn(W2[i]);
    for (int i = b * blockDim.x + t; i < INF * HH; i += NBLK * blockDim.x)
        g_w1h[i] = __float2half_rn(W1[i]);

    if (t == 0) {
        while (atomicAdd(&g_ctr, 0) < NBLK) { }
    }
    __syncthreads();

    if (t < 32) {
        int v = 0;
        for (int i = t; i < b; i += 32) v += g_bsum[i];
        #pragma unroll
        for (int o = 16; o; o >>= 1) v += __shfl_xor_sync(0xffffffffu, v, o);
        if (t == 0) sboff = v;
    }
    __syncthreads();

    int off = sboff + spart[t] - tot;
    int dd[4] = {d0, d1, d2, d3};
    #pragma unroll
    for (int i = 0; i < 4; i++) {
        int idx = base + i;
        if (idx < NN) {
            g_off[idx] = off;
            float di = rsqrtf((float)(dd[i] + 1));
            g_dinv[idx] = di;
            off += dd[i];
            #pragma unroll
            for (int q = 0; q < 4; q++) {
                float4 v = *(const float4*)&x[idx * INF + 4 * q];
                v.x *= di; v.y *= di; v.z *= di; v.w *= di;
                *(float4*)&g_x32[idx * INF + 4 * q] = v;
            }
        }
    }
}

// atomic-free CSR fill: pos = g_off[dst] + rank. 4 edges/thread, int4 loads.
__global__ void k_fill(const int* __restrict__ ei) {
    int e4 = (blockIdx.x * blockDim.x + threadIdx.x) * 4;
    if (e4 >= EE) return;
    int4 s = *(const int4*)&ei[e4];
    int4 d = *(const int4*)&ei[EE + e4];
    int4 r = *(const int4*)&g_rank[e4];
    g_csr[g_off[d.x] + r.x] = s.x;
    g_csr[g_off[d.y] + r.y] = s.y;
    g_csr[g_off[d.z] + r.z] = s.z;
    g_csr[g_off[d.w] + r.w] = s.w;
}

// FUSED layer 1: block = 128 nodes. Phase A: 8 warps x 16 nodes gather a16
// (batched fast path) -> fp16 smem tile. Phase B: per-warp m16n128k16 MMA
// (A direct from smem in fragment layout), epilogue relu*di -> g_half.
__global__ void k_l1f(const float* __restrict__ b1) {
    __shared__ __half sA[128][L1PAD];
    __shared__ __align__(16) __half sB[INF][HH + 8];
    int t = threadIdx.x, lane = t & 31, warp = t >> 5;

    if (t < 256) {
        int row = t >> 4, col = (t & 15) * 8;
        *(uint4*)&sB[row][col] = ((const uint4*)g_w1h)[t];
    }

    int q = lane & 3, e = lane >> 2;
    for (int i = 0; i < 16; i++) {
        int node = blockIdx.x * 128 + warp * 16 + i;     // uniform per warp
        float4 acc = make_float4(0.f, 0.f, 0.f, 0.f);
        float di = 0.f;
        if (node < NN) {
            int off = g_off[node];
            int deg = g_degi[node];
            di = g_dinv[node];
            if (e == 0) acc = *(const float4*)&g_x32[node * INF + 4 * q];
            int   si[4];
            float mk[4];
            #pragma unroll
            for (int k = 0; k < 4; k++) {
                int j = e + 8 * k;
                bool p = j < deg;
                si[k] = p ? g_csr[off + j] : 0;
                mk[k] = p ? 1.f : 0.f;
            }
            #pragma unroll
            for (int k = 0; k < 4; k++) {
                float4 v = *(const float4*)&g_x32[si[k] * INF + 4 * q];
                acc.x += mk[k] * v.x; acc.y += mk[k] * v.y;
                acc.z += mk[k] * v.z; acc.w += mk[k] * v.w;
            }
            for (int j = e + 32; j < deg; j += 8) {
                int s = g_csr[off + j];
                float4 v = *(const float4*)&g_x32[s * INF + 4 * q];
                acc.x += v.x; acc.y += v.y; acc.z += v.z; acc.w += v.w;
            }
            #pragma unroll
            for (int o = 4; o <= 16; o <<= 1) {
                acc.x += __shfl_xor_sync(0xffffffffu, acc.x, o);
                acc.y += __shfl_xor_sync(0xffffffffu, acc.y, o);
                acc.z += __shfl_xor_sync(0xffffffffu, acc.z, o);
                acc.w += __shfl_xor_sync(0xffffffffu, acc.w, o);
            }
        }
        if (lane < 4) {   // e==0, q=lane
            acc.x *= di; acc.y *= di; acc.z *= di; acc.w *= di;
            __half2 h0 = __floats2half2_rn(acc.x, acc.y);
            __half2 h1 = __floats2half2_rn(acc.z, acc.w);
            uint2 u;
            u.x = *(unsigned*)&h0; u.y = *(unsigned*)&h1;
            *(uint2*)&sA[warp * 16 + i][4 * lane] = u;
        }
    }
    __syncthreads();

    // MMA phase
    int lr0 = warp * 16 + (lane >> 2);
    int lr1 = lr0 + 8;
    int r0 = blockIdx.x * 128 + lr0;
    int r1 = r0 + 8;
    int tg = lane & 3;

    unsigned a0 = *(const unsigned*)&sA[lr0][2 * tg];
    unsigned a1 = *(const unsigned*)&sA[lr1][2 * tg];
    unsigned a2 = *(const unsigned*)&sA[lr0][8 + 2 * tg];
    unsigned a3 = *(const unsigned*)&sA[lr1][8 + 2 * tg];

    float acc[16][4];
    #pragma unroll
    for (int f = 0; f < 16; f++)
        acc[f][0] = acc[f][1] = acc[f][2] = acc[f][3] = 0.f;

    #pragma unroll
    for (int nc = 0; nc < 8; nc++) {
        unsigned b0, b1r, b2r, b3;
        ldmx4t(b0, b1r, b2r, b3,
               &sB[lane & 15][nc * 16 + ((lane >> 4) << 3)]);
        mma16816(acc[2 * nc + 0], a0, a1, a2, a3, b0, b1r);
        mma16816(acc[2 * nc + 1], a0, a1, a2, a3, b2r, b3);
    }

    float di0 = (r0 < NN) ? g_dinv[r0] : 0.f;
    float di1 = (r1 < NN) ? g_dinv[r1] : 0.f;
    #pragma unroll
    for (int f = 0; f < 16; f++) {
        int col = f * 8 + 2 * tg;
        float2 bias = *(const float2*)&b1[col];
        if (r0 < NN) {
            *(__half2*)&g_half[(long)r0 * HH + col] =
                __floats2half2_rn(fmaxf(acc[f][0] + bias.x, 0.f) * di0,
                                  fmaxf(acc[f][1] + bias.y, 0.f) * di0);
        }
        if (r1 < NN) {
            *(__half2*)&g_half[(long)r1 * HH + col] =
                __floats2half2_rn(fmaxf(acc[f][2] + bias.x, 0.f) * di1,
                                  fmaxf(acc[f][3] + bias.y, 0.f) * di1);
        }
    }
}

// FUSED layer 2: block = 128 nodes. Phase A: 8 warps x 16 nodes gather h1'
// from g_half -> fp16 smem tile (dynamic smem). Phase B: m16n128k128 MMA,
// epilogue relu(+b2) -> g_aggh (separate buffer: g_half still being read
// by other blocks' phase A).
__global__ void k_l2f(const float* __restrict__ b2) {
    extern __shared__ char dsm[];
    __half (*sA)[L2PAD] = (__half(*)[L2PAD])dsm;                   // 128 rows
    __half (*sB)[HH + 8] = (__half(*)[HH + 8])(dsm + 128 * L2PAD * 2);
    int t = threadIdx.x, lane = t & 31, warp = t >> 5;

    for (int i = t; i < 2048; i += 256) {
        int row = i >> 4, col = (i & 15) * 8;
        *(uint4*)&sB[row][col] = ((const uint4*)g_w2h)[i];
    }

    for (int i = 0; i < 16; i++) {
        int node = blockIdx.x * 128 + warp * 16 + i;     // uniform per warp
        float4 acc = make_float4(0.f, 0.f, 0.f, 0.f);
        if (node < NN) {
            int off = g_off[node];
            int deg = g_degi[node];
            float di = g_dinv[node];
            acc = ldh4(&g_half[node * HH + lane * 4]);
            int j = 0;
            for (; j + 4 <= deg; j += 4) {
                int s0 = g_csr[off + j + 0];
                int s1 = g_csr[off + j + 1];
                int s2 = g_csr[off + j + 2];
                int s3 = g_csr[off + j + 3];
                float4 v0 = ldh4(&g_half[s0 * HH + lane * 4]);
                float4 v1 = ldh4(&g_half[s1 * HH + lane * 4]);
                float4 v2 = ldh4(&g_half[s2 * HH + lane * 4]);
                float4 v3 = ldh4(&g_half[s3 * HH + lane * 4]);
                acc.x += (v0.x + v1.x) + (v2.x + v3.x);
                acc.y += (v0.y + v1.y) + (v2.y + v3.y);
                acc.z += (v0.z + v1.z) + (v2.z + v3.z);
                acc.w += (v0.w + v1.w) + (v2.w + v3.w);
            }
            for (; j < deg; j++) {
                int s = g_csr[off + j];
                float4 v = ldh4(&g_half[s * HH + lane * 4]);
                acc.x += v.x; acc.y += v.y; acc.z += v.z; acc.w += v.w;
            }
            acc.x *= di; acc.y *= di; acc.z *= di; acc.w *= di;
        }
        __half2 h0 = __floats2half2_rn(acc.x, acc.y);
        __half2 h1 = __floats2half2_rn(acc.z, acc.w);
        uint2 u;
        u.x = *(unsigned*)&h0; u.y = *(unsigned*)&h1;
        *(uint2*)&sA[warp * 16 + i][lane * 4] = u;
    }
    __syncthreads();

    // MMA phase
    int lr0 = warp * 16 + (lane >> 2);
    int lr1 = lr0 + 8;
    int r0 = blockIdx.x * 128 + lr0;
    int r1 = r0 + 8;
    int tg = lane & 3;

    float acc[16][4];
    #pragma unroll
    for (int f = 0; f < 16; f++)
        acc[f][0] = acc[f][1] = acc[f][2] = acc[f][3] = 0.f;

    #pragma unroll
    for (int k = 0; k < HH; k += 16) {
        unsigned a0 = *(const unsigned*)&sA[lr0][k + 2 * tg];
        unsigned a1 = *(const unsigned*)&sA[lr1][k + 2 * tg];
        unsigned a2 = *(const unsigned*)&sA[lr0][k + 8 + 2 * tg];
        unsigned a3 = *(const unsigned*)&sA[lr1][k + 8 + 2 * tg];
        #pragma unroll
        for (int nc = 0; nc < 8; nc++) {
            unsigned b0, b1, b2r, b3;
            ldmx4t(b0, b1, b2r, b3,
                   &sB[k + (lane & 15)][nc * 16 + ((lane >> 4) << 3)]);
            mma16816(acc[2 * nc + 0], a0, a1, a2, a3, b0, b1);
            mma16816(acc[2 * nc + 1], a0, a1, a2, a3, b2r, b3);
        }
    }

    #pragma unroll
    for (int f = 0; f < 16; f++) {
        int col = f * 8 + 2 * tg;
        float2 bias = *(const float2*)&b2[col];
        if (r0 < NN) {
            *(__half2*)&g_aggh[(long)r0 * HH + col] =
                __floats2half2_rn(fmaxf(acc[f][0] + bias.x, 0.f),
                                  fmaxf(acc[f][1] + bias.y, 0.f));
        }
        if (r1 < NN) {
            *(__half2*)&g_aggh[(long)r1 * HH + col] =
                __floats2half2_rn(fmaxf(acc[f][2] + bias.x, 0.f),
                                  fmaxf(acc[f][3] + bias.y, 0.f));
        }
    }
}

// One block (128 thr) per graph: segmented mean (fp16 in, fp32 acc) + heads.
// Segment bounds precomputed in g_gstart. Also re-zeroes g_degi + g_ctr.
__global__ void k_poolhead(const float* __restrict__ Wlab, const float* __restrict__ blab,
                           const float* __restrict__ Wd1, const float* __restrict__ bd1,
                           const float* __restrict__ Wd2, const float* __restrict__ bd2,
                           float* __restrict__ out) {
    __shared__ float p[HH];
    __shared__ float hid[64];
    __shared__ float warpsum[4];
    int g = blockIdx.x, t = threadIdx.x;

    int gi = g * HH + t;                 // 512*128 = 65536 >= NN
    if (gi < NN) g_degi[gi] = 0;
    if (g == 0 && t == 0) g_ctr = 0;

    int start = g_gstart[g];
    int end = g_gstart[g + 1];

    float s = 0.f;
    for (int n = start; n < end; n++) s += __half2float(g_aggh[n * HH + t]);
    float c = fmaxf((float)(end - start), 1.0f);
    float pv = s / c;
    p[t] = pv;

    float l = pv * Wlab[t];
    #pragma unroll
    for (int o = 16; o; o >>= 1) l += __shfl_xor_sync(0xffffffffu, l, o);
    if ((t & 31) == 0) warpsum[t >> 5] = l;
    __syncthreads();

    if (t < 64) {
        float h2 = bd1[t];
        #pragma unroll 4
        for (int k = 0; k < HH; k++) h2 += p[k] * Wd1[k * 64 + t];
        hid[t] = fmaxf(h2, 0.f);
    }
    __syncthreads();

    if (t == 0) {
        float z = warpsum[0] + warpsum[1] + warpsum[2] + warpsum[3] + blab[0];
        out[g] = 1.0f / (1.0f + expf(-z));
    }
    if (t < 2) {
        float s2 = bd2[t];
        #pragma unroll
        for (int k = 0; k < 64; k++) s2 += hid[k] * Wd2[k * 2 + t];
        out[GG + g * 2 + t] = s2;
    }
}

extern "C" void kernel_launch(void* const* d_in, const int* in_sizes, int n_in,
                              void* d_out, int out_size) {
    const float* x     = (const float*)d_in[0];
    const int*   ei    = (const int*)d_in[1];     // int32 (JAX x64 disabled)
    const int*   batch = (const int*)d_in[2];     // int32
    const float* W1    = (const float*)d_in[3];
    const float* b1    = (const float*)d_in[4];
    const float* W2    = (const float*)d_in[5];
    const float* b2    = (const float*)d_in[6];
    const float* Wlab  = (const float*)d_in[7];
    const float* blab  = (const float*)d_in[8];
    const float* Wd1   = (const float*)d_in[9];
    const float* bd1   = (const float*)d_in[10];
    const float* Wd2   = (const float*)d_in[11];
    const float* bd2   = (const float*)d_in[12];
    float* out = (float*)d_out;

    const int L2_SMEM = 2 * 128 * L2PAD * 2;     // sA + sB, 69632 bytes
    cudaFuncSetAttribute(k_l2f, cudaFuncAttributeMaxDynamicSharedMemorySize,
                         L2_SMEM);

    const int T = 256;
    const int EB = (EE / 4 + T - 1) / T;         // 4 edges per thread
    k_deg<<<EB, T>>>(ei, batch);                 // histogram + rank + graph bounds
    k_scanx<<<NBLK, T>>>(x, W1, W2);             // scan + offsets + W->fp16 + prescale
    k_fill<<<EB, T>>>(ei);                       // atomic-free CSR fill

    k_l1f<<<(NN + 127) / 128, T>>>(b1);          // fused agg16 + GEMM1
    k_l2f<<<(NN + 127) / 128, T, L2_SMEM>>>(b2); // fused agg128 + GEMM2
    k_poolhead<<<GG, HH>>>(Wlab, blab, Wd1, bd1, Wd2, bd2, out);
}

// round 17
// speedup vs baseline: 1.0632x; 1.0632x over previous
#include <cuda_runtime.h>
#include <cuda_fp16.h>
#include <cstdint>
#include <math.h>

#define NN 50000
#define EE 1600000
#define GG 512
#define INF 16
#define HH 128
#define NBLK 49   // ceil(50000/1024)

// ---- scratch (static device memory; no allocation anywhere) ----
__device__ float  g_x32[NN * INF];  // dinv-prescaled input features (fp32)
__device__ __half g_a16h[NN * INF]; // layer-1 aggregate, fp16 (GEMM1 A operand)
__device__ __half g_half[NN * HH];  // dinv-prescaled h1; later reused as fp16 h2 out
__device__ __half g_aggh[NN * HH];  // layer-2 aggregate, fp16 (GEMM2 A operand)
__device__ __half g_w1h[INF * HH];  // W1 in fp16
__device__ __half g_w2h[HH * HH];   // W2 in fp16
__device__ int    g_degi[NN];       // zeroed at end of every call (and statically)
__device__ int    g_off[NN];
__device__ int    g_csr[EE];        // src ids grouped by dst
__device__ int    g_rank[EE];       // edge rank within its dst bucket
__device__ float  g_dinv[NN];
__device__ int    g_bsum[NBLK];
__device__ int    g_gstart[GG + 1]; // graph segment starts (batch sorted)
__device__ int    g_ctr;            // scan barrier counter (reset by k_poolhead)

// ---------- helpers ----------
__device__ __forceinline__ float4 ldh4(const __half* p) {
    uint2 u = *(const uint2*)p;
    __half2 a, b;
    *(unsigned*)&a = u.x; *(unsigned*)&b = u.y;
    float2 fa = __half22float2(a), fb = __half22float2(b);
    return make_float4(fa.x, fa.y, fb.x, fb.y);
}
__device__ __forceinline__ void sth4(__half* p, float4 v) {
    __half2 a = __floats2half2_rn(v.x, v.y);
    __half2 b = __floats2half2_rn(v.z, v.w);
    uint2 u;
    u.x = *(unsigned*)&a; u.y = *(unsigned*)&b;
    *(uint2*)p = u;
}
__device__ __forceinline__ void ldmx4t(unsigned& r0, unsigned& r1, unsigned& r2,
                                       unsigned& r3, const void* sp) {
    unsigned addr = (unsigned)__cvta_generic_to_shared(sp);
    asm volatile("ldmatrix.sync.aligned.m8n8.x4.trans.shared.b16 {%0,%1,%2,%3}, [%4];"
                 : "=r"(r0), "=r"(r1), "=r"(r2), "=r"(r3) : "r"(addr));
}
__device__ __forceinline__ void mma16816(float* c, unsigned a0, unsigned a1,
                                         unsigned a2, unsigned a3,
                                         unsigned b0, unsigned b1) {
    asm volatile("mma.sync.aligned.m16n8k16.row.col.f32.f16.f16.f32 "
                 "{%0,%1,%2,%3}, {%4,%5,%6,%7}, {%8,%9}, {%0,%1,%2,%3};"
                 : "+f"(c[0]), "+f"(c[1]), "+f"(c[2]), "+f"(c[3])
                 : "r"(a0), "r"(a1), "r"(a2), "r"(a3), "r"(b0), "r"(b1));
}

// histogram of dst; rank = position within dst bucket. 4 edges/thread, int4
// loads. Also detects sorted-batch graph boundaries -> g_gstart.
__global__ void k_deg(const int* __restrict__ ei, const int* __restrict__ batch) {
    int tid = blockIdx.x * blockDim.x + threadIdx.x;
    if (tid < NN) {
        int b1 = batch[tid];
        int b0 = (tid == 0) ? -1 : batch[tid - 1];
        for (int g = b0 + 1; g <= b1; g++) g_gstart[g] = tid;
        if (tid == NN - 1)
            for (int g = b1 + 1; g <= GG; g++) g_gstart[g] = NN;
    }
    int e4 = tid * 4;
    if (e4 >= EE) return;                       // EE % 4 == 0 -> full int4 ok
    int4 d = *(const int4*)&ei[EE + e4];
    int4 r;
    r.x = atomicAdd(&g_degi[d.x], 1);
    r.y = atomicAdd(&g_degi[d.y], 1);
    r.z = atomicAdd(&g_degi[d.z], 1);
    r.w = atomicAdd(&g_degi[d.w], 1);
    *(int4*)&g_rank[e4] = r;
}

// 49 resident blocks: block scan + publish aggregate + W1/W2->fp16 (overlap)
// + spin barrier + global prefix + offsets + dinv + x prescale (fp32).
__global__ void k_scanx(const float* __restrict__ x, const float* __restrict__ W1,
                        const float* __restrict__ W2) {
    __shared__ int spart[256];
    __shared__ int sboff;
    int b = blockIdx.x, t = threadIdx.x;
    int base = b * 1024 + t * 4;
    int d0 = 0, d1 = 0, d2 = 0, d3 = 0;
    if (base + 3 < NN) {
        int4 q = *(const int4*)&g_degi[base];
        d0 = q.x; d1 = q.y; d2 = q.z; d3 = q.w;
    } else {
        if (base + 0 < NN) d0 = g_degi[base + 0];
        if (base + 1 < NN) d1 = g_degi[base + 1];
        if (base + 2 < NN) d2 = g_degi[base + 2];
        if (base + 3 < NN) d3 = g_degi[base + 3];
    }
    int tot = d0 + d1 + d2 + d3;
    spart[t] = tot;
    __syncthreads();
    for (int o = 1; o < 256; o <<= 1) {
        int x2 = (t >= o) ? spart[t - o] : 0;
        __syncthreads();
        spart[t] += x2;
        __syncthreads();
    }
    if (t == 255) g_bsum[b] = spart[255];
    __syncthreads();
    if (t == 0) {
        __threadfence();
        atomicAdd(&g_ctr, 1);
    }

    // overlap work while other blocks publish: W1, W2 -> fp16
    for (int i = b * blockDim.x + t; i < HH * HH; i += NBLK * blockDim.x)
        g_w2h[i] = __float2half_rn(W2[i]);
    for (int i = b * blockDim.x + t; i < INF * HH; i += NBLK * blockDim.x)
        g_w1h[i] = __float2half_rn(W1[i]);

    if (t == 0) {
        while (atomicAdd(&g_ctr, 0) < NBLK) { }
    }
    __syncthreads();

    if (t < 32) {
        int v = 0;
        for (int i = t; i < b; i += 32) v += g_bsum[i];
        #pragma unroll
        for (int o = 16; o; o >>= 1) v += __shfl_xor_sync(0xffffffffu, v, o);
        if (t == 0) sboff = v;
    }
    __syncthreads();

    int off = sboff + spart[t] - tot;
    int dd[4] = {d0, d1, d2, d3};
    #pragma unroll
    for (int i = 0; i < 4; i++) {
        int idx = base + i;
        if (idx < NN) {
            g_off[idx] = off;
            float di = rsqrtf((float)(dd[i] + 1));
            g_dinv[idx] = di;
            off += dd[i];
            #pragma unroll
            for (int q = 0; q < 4; q++) {
                float4 v = *(const float4*)&x[idx * INF + 4 * q];
                v.x *= di; v.y *= di; v.z *= di; v.w *= di;
                *(float4*)&g_x32[idx * INF + 4 * q] = v;
            }
        }
    }
}

// atomic-free CSR fill: pos = g_off[dst] + rank. 4 edges/thread, int4 loads.
__global__ void k_fill(const int* __restrict__ ei) {
    int e4 = (blockIdx.x * blockDim.x + threadIdx.x) * 4;
    if (e4 >= EE) return;
    int4 s = *(const int4*)&ei[e4];
    int4 d = *(const int4*)&ei[EE + e4];
    int4 r = *(const int4*)&g_rank[e4];
    g_csr[g_off[d.x] + r.x] = s.x;
    g_csr[g_off[d.y] + r.y] = s.y;
    g_csr[g_off[d.z] + r.z] = s.z;
    g_csr[g_off[d.w] + r.w] = s.w;
}

// warp per node, 16-dim fp32 gather with a batched (deg<=32) fast path:
// lane = (edge slot e = lane>>2, quarter q = lane&3); all 4 csr index loads
// for the fast path issue up front (independent), gathers masked via FFMA.
// a16 = di*(sum_src x'[s] + x'[n]) -> fp16 g_a16h.
__global__ void k_agg16() {
    int wid = (blockIdx.x * blockDim.x + threadIdx.x) >> 5;
    if (wid >= NN) return;
    int lane = threadIdx.x & 31;
    int q = lane & 3, e = lane >> 2;
    int off = g_off[wid];
    int deg = g_degi[wid];
    float di = g_dinv[wid];

    float4 acc = make_float4(0.f, 0.f, 0.f, 0.f);
    if (e == 0) acc = *(const float4*)&g_x32[wid * INF + 4 * q];  // self term

    // fast path: up to 32 edges, csr loads batched up front
    int   si[4];
    float mk[4];
    #pragma unroll
    for (int k = 0; k < 4; k++) {
        int j = e + 8 * k;
        bool p = j < deg;
        si[k] = p ? g_csr[off + j] : 0;
        mk[k] = p ? 1.f : 0.f;
    }
    #pragma unroll
    for (int k = 0; k < 4; k++) {
        float4 v = *(const float4*)&g_x32[si[k] * INF + 4 * q];
        acc.x += mk[k] * v.x; acc.y += mk[k] * v.y;
        acc.z += mk[k] * v.z; acc.w += mk[k] * v.w;
    }
    // remainder (deg > 32)
    for (int j = e + 32; j < deg; j += 8) {
        int s = g_csr[off + j];
        float4 v = *(const float4*)&g_x32[s * INF + 4 * q];
        acc.x += v.x; acc.y += v.y; acc.z += v.z; acc.w += v.w;
    }
    // reduce over the 8 edge slots (xor 4, 8, 16 preserve q)
    #pragma unroll
    for (int o = 4; o <= 16; o <<= 1) {
        acc.x += __shfl_xor_sync(0xffffffffu, acc.x, o);
        acc.y += __shfl_xor_sync(0xffffffffu, acc.y, o);
        acc.z += __shfl_xor_sync(0xffffffffu, acc.z, o);
        acc.w += __shfl_xor_sync(0xffffffffu, acc.w, o);
    }
    if (lane < 4) {   // e==0, q=lane
        acc.x *= di; acc.y *= di; acc.z *= di; acc.w *= di;
        sth4(&g_a16h[wid * INF + 4 * lane], acc);
    }
}

// Tensor-core GEMM1: g_half = fp16( di * relu(g_a16h @ W1h + b1) ).
__global__ void k_gemm1t(const float* __restrict__ b1) {
    __shared__ __align__(16) __half sB[INF][HH + 8];
    int t = threadIdx.x, lane = t & 31, warp = t >> 5;

    if (t < 256) {
        int row = t >> 4, col = (t & 15) * 8;
        *(uint4*)&sB[row][col] = ((const uint4*)g_w1h)[t];
    }
    __syncthreads();

    int r0 = blockIdx.x * 128 + warp * 16 + (lane >> 2);
    int r1 = r0 + 8;
    int tg = lane & 3;
    long rl0 = (long)min(r0, NN - 1) * INF;
    long rl1 = (long)min(r1, NN - 1) * INF;

    unsigned a0 = *(const unsigned*)&g_a16h[rl0 + 2 * tg];
    unsigned a1 = *(const unsigned*)&g_a16h[rl1 + 2 * tg];
    unsigned a2 = *(const unsigned*)&g_a16h[rl0 + 8 + 2 * tg];
    unsigned a3 = *(const unsigned*)&g_a16h[rl1 + 8 + 2 * tg];

    float acc[16][4];
    #pragma unroll
    for (int f = 0; f < 16; f++)
        acc[f][0] = acc[f][1] = acc[f][2] = acc[f][3] = 0.f;

    #pragma unroll
    for (int nc = 0; nc < 8; nc++) {
        unsigned b0, b1r, b2r, b3;
        ldmx4t(b0, b1r, b2r, b3,
               &sB[lane & 15][nc * 16 + ((lane >> 4) << 3)]);
        mma16816(acc[2 * nc + 0], a0, a1, a2, a3, b0, b1r);
        mma16816(acc[2 * nc + 1], a0, a1, a2, a3, b2r, b3);
    }

    float di0 = (r0 < NN) ? g_dinv[r0] : 0.f;
    float di1 = (r1 < NN) ? g_dinv[r1] : 0.f;
    #pragma unroll
    for (int f = 0; f < 16; f++) {
        int col = f * 8 + 2 * tg;
        float2 bias = *(const float2*)&b1[col];
        if (r0 < NN) {
            *(__half2*)&g_half[(long)r0 * HH + col] =
                __floats2half2_rn(fmaxf(acc[f][0] + bias.x, 0.f) * di0,
                                  fmaxf(acc[f][1] + bias.y, 0.f) * di0);
        }
        if (r1 < NN) {
            *(__half2*)&g_half[(long)r1 * HH + col] =
                __floats2half2_rn(fmaxf(acc[f][2] + bias.x, 0.f) * di1,
                                  fmaxf(acc[f][3] + bias.y, 0.f) * di1);
        }
    }
}

// warp per node: g_aggh[n] = fp16( di * (sum_src h1'[s] + h1'[n]) ).
// 8 independent 256B gathers in flight per iteration (MLP test).
__global__ void k_agg128() {
    int wid = (blockIdx.x * blockDim.x + threadIdx.x) >> 5;
    int lane = threadIdx.x & 31;
    if (wid >= NN) return;
    int off = g_off[wid];
    int deg = g_degi[wid];
    float di = g_dinv[wid];

    float4 acc = ldh4(&g_half[wid * HH + lane * 4]);

    int j = 0;
    for (; j + 8 <= deg; j += 8) {
        int si[8];
        #pragma unroll
        for (int k = 0; k < 8; k++) si[k] = g_csr[off + j + k];
        float4 v[8];
        #pragma unroll
        for (int k = 0; k < 8; k++) v[k] = ldh4(&g_half[si[k] * HH + lane * 4]);
        acc.x += ((v[0].x + v[1].x) + (v[2].x + v[3].x)) +
                 ((v[4].x + v[5].x) + (v[6].x + v[7].x));
        acc.y += ((v[0].y + v[1].y) + (v[2].y + v[3].y)) +
                 ((v[4].y + v[5].y) + (v[6].y + v[7].y));
        acc.z += ((v[0].z + v[1].z) + (v[2].z + v[3].z)) +
                 ((v[4].z + v[5].z) + (v[6].z + v[7].z));
        acc.w += ((v[0].w + v[1].w) + (v[2].w + v[3].w)) +
                 ((v[4].w + v[5].w) + (v[6].w + v[7].w));
    }
    for (; j + 4 <= deg; j += 4) {
        int s0 = g_csr[off + j + 0];
        int s1 = g_csr[off + j + 1];
        int s2 = g_csr[off + j + 2];
        int s3 = g_csr[off + j + 3];
        float4 v0 = ldh4(&g_half[s0 * HH + lane * 4]);
        float4 v1 = ldh4(&g_half[s1 * HH + lane * 4]);
        float4 v2 = ldh4(&g_half[s2 * HH + lane * 4]);
        float4 v3 = ldh4(&g_half[s3 * HH + lane * 4]);
        acc.x += (v0.x + v1.x) + (v2.x + v3.x);
        acc.y += (v0.y + v1.y) + (v2.y + v3.y);
        acc.z += (v0.z + v1.z) + (v2.z + v3.z);
        acc.w += (v0.w + v1.w) + (v2.w + v3.w);
    }
    for (; j < deg; j++) {
        int s = g_csr[off + j];
        float4 v = ldh4(&g_half[s * HH + lane * 4]);
        acc.x += v.x; acc.y += v.y; acc.z += v.z; acc.w += v.w;
    }

    acc.x *= di; acc.y *= di; acc.z *= di; acc.w *= di;
    sth4(&g_aggh[wid * HH + lane * 4], acc);
}

// Tensor-core GEMM2: g_half = fp16(relu(g_aggh @ W2h + b2)).
__global__ void k_gemm2t(const float* __restrict__ b2) {
    __shared__ __align__(16) __half sB[HH][HH + 8];
    int t = threadIdx.x, lane = t & 31, warp = t >> 5;

    for (int i = t; i < 2048; i += 256) {
        int row = i >> 4, col = (i & 15) * 8;
        *(uint4*)&sB[row][col] = ((const uint4*)g_w2h)[i];
    }
    __syncthreads();

    int r0 = blockIdx.x * 128 + warp * 16 + (lane >> 2);
    int r1 = r0 + 8;
    int tg = lane & 3;
    long rl0 = (long)min(r0, NN - 1) * HH;
    long rl1 = (long)min(r1, NN - 1) * HH;

    float acc[16][4];
    #pragma unroll
    for (int f = 0; f < 16; f++)
        acc[f][0] = acc[f][1] = acc[f][2] = acc[f][3] = 0.f;

    #pragma unroll
    for (int k = 0; k < HH; k += 16) {
        unsigned a0 = *(const unsigned*)&g_aggh[rl0 + k + 2 * tg];
        unsigned a1 = *(const unsigned*)&g_aggh[rl1 + k + 2 * tg];
        unsigned a2 = *(const unsigned*)&g_aggh[rl0 + k + 8 + 2 * tg];
        unsigned a3 = *(const unsigned*)&g_aggh[rl1 + k + 8 + 2 * tg];
        #pragma unroll
        for (int nc = 0; nc < 8; nc++) {
            unsigned b0, b1, b2r, b3;
            ldmx4t(b0, b1, b2r, b3,
                   &sB[k + (lane & 15)][nc * 16 + ((lane >> 4) << 3)]);
            mma16816(acc[2 * nc + 0], a0, a1, a2, a3, b0, b1);
            mma16816(acc[2 * nc + 1], a0, a1, a2, a3, b2r, b3);
        }
    }

    #pragma unroll
    for (int f = 0; f < 16; f++) {
        int col = f * 8 + 2 * tg;
        float2 bias = *(const float2*)&b2[col];
        if (r0 < NN) {
            *(__half2*)&g_half[(long)r0 * HH + col] =
                __floats2half2_rn(fmaxf(acc[f][0] + bias.x, 0.f),
                                  fmaxf(acc[f][1] + bias.y, 0.f));
        }
        if (r1 < NN) {
            *(__half2*)&g_half[(long)r1 * HH + col] =
                __floats2half2_rn(fmaxf(acc[f][2] + bias.x, 0.f),
                                  fmaxf(acc[f][3] + bias.y, 0.f));
        }
    }
}

// One block (128 thr) per graph: segmented mean (fp16 in, fp32 acc) + heads.
// Segment bounds precomputed in g_gstart. Also re-zeroes g_degi + g_ctr.
__global__ void k_poolhead(const float* __restrict__ Wlab, const float* __restrict__ blab,
                           const float* __restrict__ Wd1, const float* __restrict__ bd1,
                           const float* __restrict__ Wd2, const float* __restrict__ bd2,
                           float* __restrict__ out) {
    __shared__ float p[HH];
    __shared__ float hid[64];
    __shared__ float warpsum[4];
    int g = blockIdx.x, t = threadIdx.x;

    int gi = g * HH + t;                 // 512*128 = 65536 >= NN
    if (gi < NN) g_degi[gi] = 0;
    if (g == 0 && t == 0) g_ctr = 0;

    int start = g_gstart[g];
    int end = g_gstart[g + 1];

    float s = 0.f;
    for (int n = start; n < end; n++) s += __half2float(g_half[n * HH + t]);
    float c = fmaxf((float)(end - start), 1.0f);
    float pv = s / c;
    p[t] = pv;

    float l = pv * Wlab[t];
    #pragma unroll
    for (int o = 16; o; o >>= 1) l += __shfl_xor_sync(0xffffffffu, l, o);
    if ((t & 31) == 0) warpsum[t >> 5] = l;
    __syncthreads();

    if (t < 64) {
        float h2 = bd1[t];
        #pragma unroll 4
        for (int k = 0; k < HH; k++) h2 += p[k] * Wd1[k * 64 + t];
        hid[t] = fmaxf(h2, 0.f);
    }
    __syncthreads();

    if (t == 0) {
        float z = warpsum[0] + warpsum[1] + warpsum[2] + warpsum[3] + blab[0];
        out[g] = 1.0f / (1.0f + expf(-z));
    }
    if (t < 2) {
        float s2 = bd2[t];
        #pragma unroll
        for (int k = 0; k < 64; k++) s2 += hid[k] * Wd2[k * 2 + t];
        out[GG + g * 2 + t] = s2;
    }
}

extern "C" void kernel_launch(void* const* d_in, const int* in_sizes, int n_in,
                              void* d_out, int out_size) {
    const float* x     = (const float*)d_in[0];
    const int*   ei    = (const int*)d_in[1];     // int32 (JAX x64 disabled)
    const int*   batch = (const int*)d_in[2];     // int32
    const float* W1    = (const float*)d_in[3];
    const float* b1    = (const float*)d_in[4];
    const float* W2    = (const float*)d_in[5];
    const float* b2    = (const float*)d_in[6];
    const float* Wlab  = (const float*)d_in[7];
    const float* blab  = (const float*)d_in[8];
    const float* Wd1   = (const float*)d_in[9];
    const float* bd1   = (const float*)d_in[10];
    const float* Wd2   = (const float*)d_in[11];
    const float* bd2   = (const float*)d_in[12];
    float* out = (float*)d_out;

    const int T = 256;
    const int EB = (EE / 4 + T - 1) / T;         // 4 edges per thread
    k_deg<<<EB, T>>>(ei, batch);                 // histogram + rank + graph bounds
    k_scanx<<<NBLK, T>>>(x, W1, W2);             // scan + offsets + W->fp16 + prescale
    k_fill<<<EB, T>>>(ei);                       // atomic-free CSR fill

    k_agg16<<<(NN * 32 + T - 1) / T, T>>>();     // fp32 gather, batched fast path
    k_gemm1t<<<(NN + 127) / 128, T>>>(b1);       // tensor-core W1 transform
    k_agg128<<<(NN * 32 + T - 1) / T, T>>>();    // 8-deep MLP gather
    k_gemm2t<<<(NN + 127) / 128, T>>>(b2);

    k_poolhead<<<GG, HH>>>(Wlab, blab, Wd1, bd1, Wd2, bd2, out);
}